// round 5
// baseline (speedup 1.0000x reference)
#include <cuda_runtime.h>
#include <cstdint>
#include <math.h>

#define B_DIM  1024
#define H_DIM  1024
#define IN_DIM 1024
#define C_DIM  1000

#define KC 32            // K chunk
#define ASTRIDE 137      // [k][m] smem stride, %32==9 (STS conflict-free, LDS <=2-way)
#define BSTRIDE 73       // [k][n] smem stride, %32==9

#define A_OFF(b)  ((b) * (KC * ASTRIDE))
#define B_OFF(b)  (2 * KC * ASTRIDE + (b) * (KC * BSTRIDE))
#define SMEM_FLOATS (2 * KC * ASTRIDE + 2 * KC * BSTRIDE)   // 13440 floats = 53760 B
#define HID_STRIDE 65

// scratch: prod = gi * xi, [B, 4H]
__device__ float g_prod[B_DIM * 4 * H_DIM];

__device__ __forceinline__ uint32_t tf32r(float x) {
    uint32_t r;
    asm("cvt.rna.tf32.f32 %0, %1;" : "=r"(r) : "f"(x));
    return r;
}

__device__ __forceinline__ void mma8(float* d, const uint32_t* a, const uint32_t* b) {
    asm volatile(
        "mma.sync.aligned.m16n8k8.row.col.f32.tf32.tf32.f32 "
        "{%0,%1,%2,%3}, {%4,%5,%6,%7}, {%8,%9}, {%0,%1,%2,%3};"
        : "+f"(d[0]), "+f"(d[1]), "+f"(d[2]), "+f"(d[3])
        : "r"(a[0]), "r"(a[1]), "r"(a[2]), "r"(a[3]), "r"(b[0]), "r"(b[1]));
}

// One K=32 chunk. Warp tile 64(M) x 16(N).
__device__ __forceinline__ void compute_chunk(const uint32_t* As, const uint32_t* Bs,
                                              float (&acc)[32],
                                              int wm, int wn, int gid, int ctid) {
#pragma unroll
    for (int ks = 0; ks < 4; ks++) {
        uint32_t bf[2][2];
#pragma unroll
        for (int nt = 0; nt < 2; nt++) {
            int n = wn * 16 + nt * 8 + gid;
            bf[nt][0] = Bs[(ks * 8 + ctid) * BSTRIDE + n];
            bf[nt][1] = Bs[(ks * 8 + ctid + 4) * BSTRIDE + n];
        }
#pragma unroll
        for (int mt = 0; mt < 4; mt++) {
            int m = wm * 64 + mt * 16 + gid;
            uint32_t af[4];
            af[0] = As[(ks * 8 + ctid) * ASTRIDE + m];
            af[1] = As[(ks * 8 + ctid) * ASTRIDE + m + 8];
            af[2] = As[(ks * 8 + ctid + 4) * ASTRIDE + m];
            af[3] = As[(ks * 8 + ctid + 4) * ASTRIDE + m + 8];
#pragma unroll
            for (int nt = 0; nt < 2; nt++)
                mma8(&acc[mt * 8 + nt * 4], af, bf[nt]);
        }
    }
}

// LDG one chunk. A [128 rows x 32k], B [64 n x 32k] (n = sec*16+hcol gate groups).
__device__ __forceinline__ void ldg_chunk(
    int g, int brow0, int hcol0,
    const float* __restrict__ A0, const float* __restrict__ Bw0, int ld0,
    const float* __restrict__ A1, const float* __restrict__ Bw1, int ld1,
    int lrow, int lkg, float4 (&ra)[4], float4 (&rb)[2]) {
    int ph = g >> 5, k0 = (g & 31) * KC;
    const float* A = ph ? A1 : A0;
    const float* Bw = ph ? Bw1 : Bw0;
    int ld = ph ? ld1 : ld0;
    int kf = k0 + lkg * 4;
    bool ok = kf < ld;            // contiguous: kmax == ld; ld % 4 == 0
    const float4 z4 = make_float4(0.f, 0.f, 0.f, 0.f);
#pragma unroll
    for (int p = 0; p < 4; p++) {
        int m = p * 32 + lrow;
        ra[p] = ok ? *(const float4*)&A[(size_t)(brow0 + m) * ld + kf] : z4;
    }
#pragma unroll
    for (int p = 0; p < 2; p++) {
        int n = p * 32 + lrow;
        int rg = ((n >> 4) << 10) + hcol0 + (n & 15);   // gate row = sec*1024 + hcol
        rb[p] = ok ? *(const float4*)&Bw[(size_t)rg * ld + kf] : z4;
    }
}

__device__ __forceinline__ void sts_chunk(uint32_t* As, uint32_t* Bs,
                                          int lrow, int lkg,
                                          const float4 (&ra)[4], const float4 (&rb)[2]) {
#pragma unroll
    for (int p = 0; p < 4; p++) {
        const float* v = (const float*)&ra[p];
#pragma unroll
        for (int j = 0; j < 4; j++)
            As[(lkg * 4 + j) * ASTRIDE + p * 32 + lrow] = tf32r(v[j]);
    }
#pragma unroll
    for (int p = 0; p < 2; p++) {
        const float* v = (const float*)&rb[p];
#pragma unroll
        for (int j = 0; j < 4; j++)
            Bs[(lkg * 4 + j) * BSTRIDE + p * 32 + lrow] = tf32r(v[j]);
    }
}

// MODE 0: acc0 = A0@B0 (xi), acc1 = A1@B1 (gi); write prod = acc1*acc0.
// MODE 1: acc0 = hs, acc1 = gs; z = prod + gs*hs; sigmoid; LSTM epilogue.
template <int MODE>
__global__ void __launch_bounds__(256, 2) scn_half_kernel(
    const float* __restrict__ A0, const float* __restrict__ Bw0, int ld0,
    const float* __restrict__ A1, const float* __restrict__ Bw1, int ld1,
    const float* __restrict__ c_state, float* __restrict__ out) {
    extern __shared__ uint32_t smf[];
    const int tid = threadIdx.x, lane = tid & 31, wid = tid >> 5;
    const int gid = lane >> 2, ctid = lane & 3;
    const int wm = wid >> 2, wn = wid & 3;           // warp grid 2(M) x 4(N)
    const int lrow = tid >> 3, lkg = tid & 7;
    const int hcol0 = blockIdx.x * 16;
    const int brow0 = blockIdx.y * 128;

    float acc0[32] = {}, acc1[32] = {};
    float4 ra[4], rb[2];

    ldg_chunk(0, brow0, hcol0, A0, Bw0, ld0, A1, Bw1, ld1, lrow, lkg, ra, rb);

    for (int g = 0; g < 64; g++) {
        const int buf = g & 1;
        sts_chunk(smf + A_OFF(buf), smf + B_OFF(buf), lrow, lkg, ra, rb);
        __syncthreads();
        if (g + 1 < 64)
            ldg_chunk(g + 1, brow0, hcol0, A0, Bw0, ld0, A1, Bw1, ld1, lrow, lkg, ra, rb);
        if (g < 32)
            compute_chunk(smf + A_OFF(buf), smf + B_OFF(buf), acc0, wm, wn, gid, ctid);
        else
            compute_chunk(smf + A_OFF(buf), smf + B_OFF(buf), acc1, wm, wn, gid, ctid);
        __syncthreads();
        // note: two barriers per chunk (compute must finish before next STS to same buf
        // is NOT needed with double buffer; but STS(g+2) targets buf again after one more
        // sync -- the first barrier of iteration g+1 only orders STS(g+1). Keep the
        // trailing barrier to order compute(g, buf) before STS(g+2, buf).)
    }
    __syncthreads();

    if (MODE == 0) {
        // write prod = gi * xi to scratch in [b][sec*1024 + hcol] layout
#pragma unroll
        for (int mt = 0; mt < 4; mt++)
#pragma unroll
            for (int nt = 0; nt < 2; nt++)
#pragma unroll
                for (int c = 0; c < 4; c++) {
                    int i = mt * 8 + nt * 4 + c;
                    int m = wm * 64 + mt * 16 + gid + ((c >> 1) ? 8 : 0);
                    int n = wn * 16 + nt * 8 + ctid * 2 + (c & 1);
                    size_t idx = (size_t)(brow0 + m) * 4096 + ((n >> 4) << 10) + hcol0 + (n & 15);
                    g_prod[idx] = acc1[i] * acc0[i];
                }
    } else {
        float* hid = (float*)smf;   // reuse smem: 128 x 65 floats
#pragma unroll
        for (int mt = 0; mt < 4; mt++)
#pragma unroll
            for (int nt = 0; nt < 2; nt++)
#pragma unroll
                for (int c = 0; c < 4; c++) {
                    int i = mt * 8 + nt * 4 + c;
                    int m = wm * 64 + mt * 16 + gid + ((c >> 1) ? 8 : 0);
                    int n = wn * 16 + nt * 8 + ctid * 2 + (c & 1);
                    size_t idx = (size_t)(brow0 + m) * 4096 + ((n >> 4) << 10) + hcol0 + (n & 15);
                    float z = g_prod[idx] + acc1[i] * acc0[i];
                    hid[m * HID_STRIDE + n] = 1.0f / (1.0f + expf(-z));
                }
        __syncthreads();
        // LSTM combine: local n = sec*16 + j; secs = i, f, o, c_cand
        int m = tid >> 1;
        int j0 = (tid & 1) * 8;
        const float* row = hid + m * HID_STRIDE;
        size_t gbase = (size_t)(brow0 + m) * H_DIM + hcol0 + j0;
#pragma unroll
        for (int i = 0; i < 8; i++) {
            int j = j0 + i;
            float it = row[j];
            float ft = row[16 + j];
            float ot = row[32 + j];
            float cc = row[48 + j];
            float cs = c_state[gbase + i];
            float ct = it * cc + ft * cs;
            float ht = ot * tanhf(ct);
            out[gbase + i] = ht;
            out[(size_t)B_DIM * H_DIM + gbase + i] = ct;
        }
    }
}

extern "C" void kernel_launch(void* const* d_in, const int* in_sizes, int n_in,
                              void* d_out, int out_size) {
    const float* core_input = (const float*)d_in[0];
    const float* h_state    = (const float*)d_in[1];
    const float* c_state    = (const float*)d_in[2];
    const float* concept    = (const float*)d_in[3];
    const float* W_in       = (const float*)d_in[4];
    const float* W_st       = (const float*)d_in[5];
    const float* W_ci       = (const float*)d_in[6];
    const float* W_cs       = (const float*)d_in[7];
    float* out = (float*)d_out;

    static bool configured = false;
    if (!configured) {
        cudaFuncSetAttribute(scn_half_kernel<0>,
                             cudaFuncAttributeMaxDynamicSharedMemorySize, SMEM_FLOATS * 4);
        cudaFuncSetAttribute(scn_half_kernel<1>,
                             cudaFuncAttributeMaxDynamicSharedMemorySize, SMEM_FLOATS * 4);
        configured = true;
    }

    dim3 grid(64, 8);   // 64 h-col tiles x 8 batch tiles = 512 CTAs
    // Kernel A: xi = core@W_in, gi = concept@W_ci, prod = gi*xi
    scn_half_kernel<0><<<grid, 256, SMEM_FLOATS * 4>>>(
        core_input, W_in, IN_DIM, concept, W_ci, C_DIM, c_state, out);
    // Kernel B: hs = h@W_st, gs = concept@W_cs, z = prod + gs*hs, LSTM epilogue
    scn_half_kernel<1><<<grid, 256, SMEM_FLOATS * 4>>>(
        h_state, W_st, H_DIM, concept, W_cs, C_DIM, c_state, out);
}

// round 6
// speedup vs baseline: 1.5179x; 1.5179x over previous
#include <cuda_runtime.h>
#include <cstdint>
#include <math.h>

#define B_DIM  1024
#define H_DIM  1024
#define KPAD   1024    // all K dims padded to 1024 (zeros contribute nothing)

#define ASTR 36                       // smem floats per row, 36 % 32 == 4 -> conflict-free LDS
#define A_BYTES (128 * ASTR * 4)      // 18432
#define B_BYTES (64 * ASTR * 4)       // 9216
#define STAGE_BYTES (A_BYTES + 2 * B_BYTES)   // 36864
#define NSTAGE 4
#define SMEM_BYTES (NSTAGE * STAGE_BYTES)     // 147456
#define HID_STRIDE 65

// tf32-pre-rounded operands, padded to KPAD cols. __device__ globals are
// zero-initialized, and the cvt pass never writes the pad -> pad stays 0.
__device__ float cvt_core[B_DIM * KPAD];
__device__ float cvt_h[B_DIM * KPAD];
__device__ float cvt_concept[B_DIM * KPAD];
__device__ float cvt_Win[4 * H_DIM * KPAD];
__device__ float cvt_Wst[4 * H_DIM * KPAD];
__device__ float cvt_Wci[4 * H_DIM * KPAD];
__device__ float cvt_Wcs[4 * H_DIM * KPAD];

__device__ __forceinline__ uint32_t smem_u32(const void* p) {
    uint32_t a;
    asm("{ .reg .u64 t; cvta.to.shared.u64 t, %1; cvt.u32.u64 %0, t; }" : "=r"(a) : "l"(p));
    return a;
}
__device__ __forceinline__ void cpa16(uint32_t dst, const float* src) {
    asm volatile("cp.async.cg.shared.global [%0], [%1], 16;"
                 :: "r"(dst), "l"(__cvta_generic_to_global(src)) : "memory");
}
#define CP_COMMIT() asm volatile("cp.async.commit_group;" ::: "memory")
#define CP_WAIT2()  asm volatile("cp.async.wait_group 2;" ::: "memory")

__device__ __forceinline__ void mma8(float* d, const uint32_t* a, const uint32_t* b) {
    asm volatile(
        "mma.sync.aligned.m16n8k8.row.col.f32.tf32.tf32.f32 "
        "{%0,%1,%2,%3}, {%4,%5,%6,%7}, {%8,%9}, {%0,%1,%2,%3};"
        : "+f"(d[0]), "+f"(d[1]), "+f"(d[2]), "+f"(d[3])
        : "r"(a[0]), "r"(a[1]), "r"(a[2]), "r"(a[3]), "r"(b[0]), "r"(b[1]));
}

// Warp tile 64(M) x 16(N). Layout: As[m][k] stride ASTR, Bs[n][k] stride ASTR.
__device__ __forceinline__ void compute_chunk(const uint32_t* As, const uint32_t* Bs,
                                              float (&acc)[32],
                                              int wm, int wn, int gid, int ctid) {
    const uint32_t* Aw = As + (wm * 64 + gid) * ASTR + ctid;
    const uint32_t* Bw = Bs + (wn * 16 + gid) * ASTR + ctid;
#pragma unroll
    for (int ks = 0; ks < 4; ks++) {
        uint32_t bf[2][2];
#pragma unroll
        for (int nt = 0; nt < 2; nt++) {
            bf[nt][0] = Bw[nt * 8 * ASTR + ks * 8];
            bf[nt][1] = Bw[nt * 8 * ASTR + ks * 8 + 4];
        }
#pragma unroll
        for (int mt = 0; mt < 4; mt++) {
            uint32_t af[4];
            af[0] = Aw[(mt * 16    ) * ASTR + ks * 8];
            af[1] = Aw[(mt * 16 + 8) * ASTR + ks * 8];
            af[2] = Aw[(mt * 16    ) * ASTR + ks * 8 + 4];
            af[3] = Aw[(mt * 16 + 8) * ASTR + ks * 8 + 4];
#pragma unroll
            for (int nt = 0; nt < 2; nt++)
                mma8(&acc[mt * 8 + nt * 4], af, bf[nt]);
        }
    }
}

__device__ __forceinline__ void compute_chunk2(const uint32_t* As, const uint32_t* B0s,
                                               const uint32_t* B1s,
                                               float (&acc0)[32], float (&acc1)[32],
                                               int wm, int wn, int gid, int ctid) {
    const uint32_t* Aw  = As  + (wm * 64 + gid) * ASTR + ctid;
    const uint32_t* Bw0 = B0s + (wn * 16 + gid) * ASTR + ctid;
    const uint32_t* Bw1 = B1s + (wn * 16 + gid) * ASTR + ctid;
#pragma unroll
    for (int ks = 0; ks < 4; ks++) {
        uint32_t bf0[2][2], bf1[2][2];
#pragma unroll
        for (int nt = 0; nt < 2; nt++) {
            bf0[nt][0] = Bw0[nt * 8 * ASTR + ks * 8];
            bf0[nt][1] = Bw0[nt * 8 * ASTR + ks * 8 + 4];
            bf1[nt][0] = Bw1[nt * 8 * ASTR + ks * 8];
            bf1[nt][1] = Bw1[nt * 8 * ASTR + ks * 8 + 4];
        }
#pragma unroll
        for (int mt = 0; mt < 4; mt++) {
            uint32_t af[4];
            af[0] = Aw[(mt * 16    ) * ASTR + ks * 8];
            af[1] = Aw[(mt * 16 + 8) * ASTR + ks * 8];
            af[2] = Aw[(mt * 16    ) * ASTR + ks * 8 + 4];
            af[3] = Aw[(mt * 16 + 8) * ASTR + ks * 8 + 4];
#pragma unroll
            for (int nt = 0; nt < 2; nt++) {
                mma8(&acc0[mt * 8 + nt * 4], af, bf0[nt]);
                mma8(&acc1[mt * 8 + nt * 4], af, bf1[nt]);
            }
        }
    }
}

// Issue cp.async loads for chunk g into stage slot (g & 3).
__device__ __forceinline__ void issue_chunk(int g, uint32_t sbase, int brow0, int hcol0,
                                            int lrow, int lkg) {
    const int ph = g >> 5, k0 = (g & 31) * 32;
    const float* A  = (ph == 0) ? cvt_core : (ph == 1) ? cvt_h   : cvt_concept;
    const float* B0 = (ph == 0) ? cvt_Win  : (ph == 1) ? cvt_Wst : cvt_Wci;
    uint32_t st = sbase + (uint32_t)(g & 3) * STAGE_BYTES;
    const int kf = k0 + lkg * 4;
#pragma unroll
    for (int p = 0; p < 4; p++) {
        int m = p * 32 + lrow;
        cpa16(st + (uint32_t)((m * ASTR + lkg * 4) * 4),
              A + (size_t)(brow0 + m) * KPAD + kf);
    }
#pragma unroll
    for (int p = 0; p < 2; p++) {
        int n = p * 32 + lrow;
        int rg = ((n >> 4) << 10) + hcol0 + (n & 15);   // gate row = sec*1024 + hcol
        uint32_t doff = (uint32_t)((n * ASTR + lkg * 4) * 4);
        cpa16(st + A_BYTES + doff, B0 + (size_t)rg * KPAD + kf);
        if (ph == 2)
            cpa16(st + A_BYTES + B_BYTES + doff, cvt_Wcs + (size_t)rg * KPAD + kf);
    }
    CP_COMMIT();
}

__global__ void __launch_bounds__(256, 1) scn_mma_kernel(
    const float* __restrict__ c_state, float* __restrict__ out) {
    extern __shared__ float smf[];
    const uint32_t sbase = smem_u32(smf);
    const int tid = threadIdx.x, lane = tid & 31, wid = tid >> 5;
    const int gid = lane >> 2, ctid = lane & 3;
    const int wm = wid >> 2, wn = wid & 3;           // warp grid 2(M) x 4(N)
    const int lrow = tid >> 3, lkg = tid & 7;
    const int hcol0 = blockIdx.x * 16;
    const int brow0 = blockIdx.y * 128;

    float axi[32] = {}, ahs[32] = {}, agi[32] = {}, ags[32] = {};

    // prologue: prefetch 3 chunks
    issue_chunk(0, sbase, brow0, hcol0, lrow, lkg);
    issue_chunk(1, sbase, brow0, hcol0, lrow, lkg);
    issue_chunk(2, sbase, brow0, hcol0, lrow, lkg);

    for (int g = 0; g < 96; g++) {
        CP_WAIT2();            // stage g complete (3 groups pending max -> wait to 2)
        __syncthreads();
        if (g + 3 < 96) issue_chunk(g + 3, sbase, brow0, hcol0, lrow, lkg);
        else            CP_COMMIT();   // empty group keeps the pending count exact

        const uint32_t* st = (const uint32_t*)smf + (size_t)(g & 3) * (STAGE_BYTES / 4);
        const uint32_t* Bs = st + A_BYTES / 4;
        if (g < 32)
            compute_chunk(st, Bs, axi, wm, wn, gid, ctid);
        else if (g < 64)
            compute_chunk(st, Bs, ahs, wm, wn, gid, ctid);
        else
            compute_chunk2(st, Bs, Bs + B_BYTES / 4, agi, ags, wm, wn, gid, ctid);
        // stage slot (g+3)&3 == (g-1)&3: all warps finished compute(g-1) before the
        // barrier above, so overwriting it via cp.async after the barrier is safe.
    }
    __syncthreads();

    // ---- fused epilogue: hidden = sigmoid(gi*xi + gs*hs) staged in smem ----
    float* hid = smf;   // reuse: 128 x 65 floats
#pragma unroll
    for (int mt = 0; mt < 4; mt++)
#pragma unroll
        for (int nt = 0; nt < 2; nt++)
#pragma unroll
            for (int c = 0; c < 4; c++) {
                int i = mt * 8 + nt * 4 + c;
                int m = wm * 64 + mt * 16 + gid + ((c >> 1) ? 8 : 0);
                int n = wn * 16 + nt * 8 + ctid * 2 + (c & 1);
                float z = agi[i] * axi[i] + ags[i] * ahs[i];
                hid[m * HID_STRIDE + n] = 1.0f / (1.0f + expf(-z));
            }
    __syncthreads();

    // LSTM combine: local n = sec*16 + j; secs = i, f, o, c_cand
    {
        int m = tid >> 1;
        int j0 = (tid & 1) * 8;
        const float* row = hid + m * HID_STRIDE;
        size_t gbase = (size_t)(brow0 + m) * H_DIM + hcol0 + j0;
#pragma unroll
        for (int i = 0; i < 8; i++) {
            int j = j0 + i;
            float it = row[j];
            float ft = row[16 + j];
            float ot = row[32 + j];
            float cc = row[48 + j];
            float cs = c_state[gbase + i];
            float ct = it * cc + ft * cs;
            float ht = ot * tanhf(ct);
            out[gbase + i] = ht;
            out[(size_t)B_DIM * H_DIM + gbase + i] = ct;
        }
    }
}

// ---------------- tf32 round + pad pre-pass ----------------
// Reads [rows x cols] (cols % 4 == 0), writes tf32-rounded into [rows x KPAD].
template <int J>
__global__ void __launch_bounds__(256) cvt_kernel(const float4* __restrict__ src,
                                                  int n4, int c4) {
    int i = blockIdx.x * blockDim.x + threadIdx.x;
    if (i >= n4) return;
    float4 v = src[i];
    uint32_t a, b, c, e;
    asm("cvt.rna.tf32.f32 %0, %1;" : "=r"(a) : "f"(v.x));
    asm("cvt.rna.tf32.f32 %0, %1;" : "=r"(b) : "f"(v.y));
    asm("cvt.rna.tf32.f32 %0, %1;" : "=r"(c) : "f"(v.z));
    asm("cvt.rna.tf32.f32 %0, %1;" : "=r"(e) : "f"(v.w));
    float4 o;
    o.x = __uint_as_float(a); o.y = __uint_as_float(b);
    o.z = __uint_as_float(c); o.w = __uint_as_float(e);
    float* dst = (J == 0) ? cvt_core : (J == 1) ? cvt_h : (J == 2) ? cvt_concept
               : (J == 3) ? cvt_Win  : (J == 4) ? cvt_Wst
               : (J == 5) ? cvt_Wci  : cvt_Wcs;
    int row = i / c4, col = i - row * c4;
    ((float4*)dst)[row * (KPAD / 4) + col] = o;
}

template <int J>
static void launch_cvt(const float* src, int rows, int cols) {
    int n4 = rows * cols / 4;
    cvt_kernel<J><<<(n4 + 255) / 256, 256>>>((const float4*)src, n4, cols / 4);
}

extern "C" void kernel_launch(void* const* d_in, const int* in_sizes, int n_in,
                              void* d_out, int out_size) {
    const float* core_input = (const float*)d_in[0];
    const float* h_state    = (const float*)d_in[1];
    const float* c_state    = (const float*)d_in[2];
    const float* concept    = (const float*)d_in[3];
    const float* W_in       = (const float*)d_in[4];
    const float* W_st       = (const float*)d_in[5];
    const float* W_ci       = (const float*)d_in[6];
    const float* W_cs       = (const float*)d_in[7];
    float* out = (float*)d_out;

    static bool configured = false;
    if (!configured) {
        cudaFuncSetAttribute(scn_mma_kernel,
                             cudaFuncAttributeMaxDynamicSharedMemorySize, SMEM_BYTES);
        configured = true;
    }

    launch_cvt<0>(core_input, B_DIM, 1024);
    launch_cvt<1>(h_state,    B_DIM, 1024);
    launch_cvt<2>(concept,    B_DIM, 1000);
    launch_cvt<3>(W_in,  4 * H_DIM, 1024);
    launch_cvt<4>(W_st,  4 * H_DIM, 1024);
    launch_cvt<5>(W_ci,  4 * H_DIM, 1000);
    launch_cvt<6>(W_cs,  4 * H_DIM, 1000);

    dim3 grid(64, 8);   // 64 h-col tiles x 8 batch tiles = 512 CTAs
    scn_mma_kernel<<<grid, 256, SMEM_BYTES>>>(c_state, out);
}